// round 14
// baseline (speedup 1.0000x reference)
#include <cuda_runtime.h>
#include <math.h>
#include <cstdint>

// ---------------------------------------------------------------------------
// GroupAttentionLayer: B=4, H=W=64, C=256, RF=STRIDE=16 (windows tile exactly)
//   Q,K,V = leaky(BN(x @ W))                       [16384, 256] each
//   yout  = leaky(Q K^T / 16) V   per batch        FUSED (no P materialization)
//   out   = softmax_spatial( s_c * yout ),  s_c = g1_c * rsqrt(var_c(yout)+eps)
//   (BN shift cancels inside the spatial softmax)
// ---------------------------------------------------------------------------

#define PROJ_ELEMS 4194304ull      // 16384*256
#define QB_STRIDE  1048576ll       // 4096*256

static __device__ __align__(16) float g_X[PROJ_ELEMS];          // tf32-rounded x
static __device__ __align__(16) float g_Wt[3ull * 65536ull];    // W^T, tf32-rounded
static __device__ __align__(16) float g_Y[3ull * PROJ_ELEMS];   // Q,K,V
static __device__ __align__(16) float g_Vt[4ull * 1048576ull];  // V^T [b][c][i]
static __device__ __align__(16) float g_yout[PROJ_ELEMS];
static __device__ __align__(16) float g_ps[3 * 256 * 256];
static __device__ __align__(16) float g_pq[3 * 256 * 256];
static __device__ __align__(16) float g_ps2[256 * 256];
static __device__ __align__(16) float g_pq2[256 * 256];
static __device__ __align__(16) float g_scale[3 * 256];
static __device__ __align__(16) float g_shift[3 * 256];
static __device__ __align__(16) float g_sscale[256];

#define LEAKY(v) ((v) > 0.f ? (v) : 0.3f * (v))

__device__ __forceinline__ float tf32r(float x) {
    uint32_t u;
    asm("cvt.rna.tf32.f32 %0, %1;" : "=r"(u) : "f"(x));
    return __uint_as_float(u);
}

// mma.sync m16n8k8 tf32: D += A*B, row.col, fp32 accum.
__device__ __forceinline__ void mma_tf32(float* d, const uint32_t* a, const uint32_t* b)
{
    asm volatile(
        "mma.sync.aligned.m16n8k8.row.col.f32.tf32.tf32.f32 "
        "{%0,%1,%2,%3}, {%4,%5,%6,%7}, {%8,%9}, {%0,%1,%2,%3};\n"
        : "+f"(d[0]), "+f"(d[1]), "+f"(d[2]), "+f"(d[3])
        : "r"(a[0]), "r"(a[1]), "r"(a[2]), "r"(a[3]), "r"(b[0]), "r"(b[1]));
}

__device__ __forceinline__ void ldmatrix_x4(uint32_t* r, uint32_t addr)
{
    asm volatile("ldmatrix.sync.aligned.m8n8.x4.shared.b16 {%0,%1,%2,%3}, [%4];"
                 : "=r"(r[0]), "=r"(r[1]), "=r"(r[2]), "=r"(r[3]) : "r"(addr));
}
__device__ __forceinline__ void ldmatrix_x2(uint32_t* r, uint32_t addr)
{
    asm volatile("ldmatrix.sync.aligned.m8n8.x2.shared.b16 {%0,%1}, [%2];"
                 : "=r"(r[0]), "=r"(r[1]) : "r"(addr));
}

__device__ __forceinline__ uint32_t smem_u32(const void* p) {
    uint32_t a;
    asm("{ .reg .u64 t; cvta.to.shared.u64 t, %1; cvt.u32.u64 %0, t; }"
        : "=r"(a) : "l"(p));
    return a;
}

__device__ __forceinline__ void cp_async16(uint32_t saddr, const void* gptr)
{
    asm volatile("cp.async.cg.shared.global [%0], [%1], 16;\n"
                 :: "r"(saddr), "l"(gptr));
}
__device__ __forceinline__ void cp_commit()
{
    asm volatile("cp.async.commit_group;\n" ::: "memory");
}
template <int N>
__device__ __forceinline__ void cp_wait()
{
    asm volatile("cp.async.wait_group %0;\n" :: "n"(N) : "memory");
}

// ===========================================================================
// Fused attention: per block, 64 Q-rows x full 4096 kl x 256 channels.
//   for each kl tile (128 positions):
//     P = tf32r(leaky(Q K^T / 16))  [64x128]  (regs -> swizzled SMEM)
//     acc2 += P V_tile              [64x256]
// SMEM (dynamic, 192KB): Qs 64K | Kc 2x16K | Ps 32K | Vc 2x32K
// 8 warps: 2(M) x 4(N).  GEMM1 warp tile 32x32; GEMM2 warp tile 32x64.
// ===========================================================================
__global__ __launch_bounds__(256, 1)
void fused_attn(const float* __restrict__ Qg, const float* __restrict__ Kg,
                const float* __restrict__ Vtg, float* __restrict__ Og)
{
    extern __shared__ __align__(16) char smemc[];
    const uint32_t sQ = smem_u32(smemc);
    const uint32_t sK = sQ + 65536;
    const uint32_t sP = sQ + 98304;
    const uint32_t sV = sQ + 131072;
    float* Psf = (float*)(smemc + 98304);

    const int b = blockIdx.z;
    const int m0 = blockIdx.x * 64;
    Qg += (size_t)b * 1048576ull + (size_t)m0 * 256;
    Kg += (size_t)b * 1048576ull;
    Vtg += (size_t)b * 1048576ull;

    const int tid = threadIdx.x;
    const int wid = tid >> 5;
    const int lane = tid & 31;
    const int mw = (wid & 1) * 32;      // warp m offset (both GEMMs)
    const int nw1 = (wid >> 1) * 32;    // GEMM1 n offset (of 128)
    const int nw2 = (wid >> 1) * 64;    // GEMM2 n offset (of 256)

    const int lj = lane >> 3, lr = lane & 7;
    const int a_row_in = lr + ((lj & 1) << 3);
    const int a_k4off = lj >> 1;
    const int b_row_in = lr;
    const int b_k4off = lj & 1;

    float acc2[2][8][4];
#pragma unroll
    for (int i = 0; i < 2; i++)
#pragma unroll
        for (int j = 0; j < 8; j++)
#pragma unroll
            for (int e = 0; e < 4; e++) acc2[i][j][e] = 0.f;

    // ---- prologue: Qs (64x256, swizzled) + K(0,0) in one cp.async group ----
#pragma unroll
    for (int i = 0; i < 16; i++) {
        int idx = i * 256 + tid;
        int r = idx >> 6, k4 = idx & 63;
        int kg = k4 >> 3, k4l = k4 & 7;
        uint32_t off = (uint32_t)(r * 1024 + kg * 128 + ((k4l ^ (r & 7)) << 4));
        cp_async16(sQ + off, Qg + (size_t)r * 256 + 4 * k4);
    }
#pragma unroll
    for (int i = 0; i < 4; i++) {
        int idx = i * 256 + tid;
        int r = idx >> 3, k4 = idx & 7;
        uint32_t off = (uint32_t)(r * 128 + ((k4 ^ (r & 7)) << 4));
        cp_async16(sK + off, Kg + (size_t)r * 256 + 4 * k4);
    }
    cp_commit();

    for (int t = 0; t < 32; t++) {
        float acc1[2][4][4];
#pragma unroll
        for (int i = 0; i < 2; i++)
#pragma unroll
            for (int j = 0; j < 4; j++)
#pragma unroll
                for (int e = 0; e < 4; e++) acc1[i][j][e] = 0.f;

        // ================= GEMM1: P = Q K^T over 8 k-chunks =================
        for (int kc = 0; kc < 8; kc++) {
            if (kc < 7) {
                // next K chunk into other buffer
                uint32_t bufo = (uint32_t)(((kc + 1) & 1) * 16384);
#pragma unroll
                for (int i = 0; i < 4; i++) {
                    int idx = i * 256 + tid;
                    int r = idx >> 3, k4 = idx & 7;
                    uint32_t off = bufo + (uint32_t)(r * 128 + ((k4 ^ (r & 7)) << 4));
                    cp_async16(sK + off,
                        Kg + (size_t)(t * 128 + r) * 256 + (kc + 1) * 32 + 4 * k4);
                }
            } else {
                // V chunk (t, 0) into Vc buffer 0
#pragma unroll
                for (int i = 0; i < 8; i++) {
                    int idx = i * 256 + tid;
                    int r = idx >> 3, k4 = idx & 7;
                    uint32_t off = (uint32_t)(r * 128 + ((k4 ^ (r & 7)) << 4));
                    cp_async16(sV + off,
                        Vtg + (size_t)r * 4096 + t * 128 + 4 * k4);
                }
            }
            cp_commit();
            cp_wait<1>();
            __syncthreads();

            const uint32_t bK = sK + (uint32_t)((kc & 1) * 16384);
#pragma unroll
            for (int ks = 0; ks < 4; ks++) {
                uint32_t af[2][4], bf[4][2];
                int k4a = ks * 2 + a_k4off;
                int k4b = ks * 2 + b_k4off;
#pragma unroll
                for (int ma = 0; ma < 2; ma++) {
                    int rowm = mw + ma * 16 + a_row_in;
                    ldmatrix_x4(af[ma], sQ + (uint32_t)(rowm * 1024 + kc * 128
                                              + ((k4a ^ (rowm & 7)) << 4)));
                }
#pragma unroll
                for (int na = 0; na < 4; na++) {
                    int rown = nw1 + na * 8 + b_row_in;
                    ldmatrix_x2(bf[na], bK + (uint32_t)(rown * 128
                                              + ((k4b ^ (rown & 7)) << 4)));
                }
#pragma unroll
                for (int ma = 0; ma < 2; ma++)
#pragma unroll
                    for (int na = 0; na < 4; na++)
                        mma_tf32(acc1[ma][na], af[ma], bf[na]);
            }
            __syncthreads();
        }

        // ---- P tile -> swizzled SMEM (leaky + /16 + tf32 round) ----
        {
            const int pr0 = mw + (lane >> 2);
            const int pc0 = nw1 + (lane & 3) * 2;
#pragma unroll
            for (int ma = 0; ma < 2; ma++)
#pragma unroll
                for (int na = 0; na < 4; na++) {
                    int c = pc0 + na * 8;
                    int kg = c >> 5;
                    int k4l = (c >> 2) & 7;
                    int ci = c & 3;
#pragma unroll
                    for (int h = 0; h < 2; h++) {
                        int r = pr0 + ma * 16 + h * 8;
                        float v0 = acc1[ma][na][2 * h + 0] * 0.0625f;
                        float v1 = acc1[ma][na][2 * h + 1] * 0.0625f;
                        v0 = tf32r(LEAKY(v0));
                        v1 = tf32r(LEAKY(v1));
                        int off = r * 128 + kg * 32 + ((k4l ^ (r & 7)) << 2) + ci;
                        *(float2*)&Psf[off] = make_float2(v0, v1);
                    }
                }
        }
        __syncthreads();

        // ================= GEMM2: acc2 += P V over 4 k-chunks ===============
        for (int vc = 0; vc < 4; vc++) {
            if (vc < 3) {
                uint32_t bufo = (uint32_t)(((vc + 1) & 1) * 32768);
#pragma unroll
                for (int i = 0; i < 8; i++) {
                    int idx = i * 256 + tid;
                    int r = idx >> 3, k4 = idx & 7;
                    uint32_t off = bufo + (uint32_t)(r * 128 + ((k4 ^ (r & 7)) << 4));
                    cp_async16(sV + off,
                        Vtg + (size_t)r * 4096 + t * 128 + (vc + 1) * 32 + 4 * k4);
                }
            } else if (t < 31) {
                // K chunk (t+1, 0) into Kc buffer 0
#pragma unroll
                for (int i = 0; i < 4; i++) {
                    int idx = i * 256 + tid;
                    int r = idx >> 3, k4 = idx & 7;
                    uint32_t off = (uint32_t)(r * 128 + ((k4 ^ (r & 7)) << 4));
                    cp_async16(sK + off,
                        Kg + (size_t)((t + 1) * 128 + r) * 256 + 4 * k4);
                }
            }
            cp_commit();
            cp_wait<1>();
            __syncthreads();

            const uint32_t bV = sV + (uint32_t)((vc & 1) * 32768);
#pragma unroll
            for (int ks = 0; ks < 4; ks++) {
                uint32_t af[2][4], bf[8][2];
                int k4a = ks * 2 + a_k4off;
                int k4b = ks * 2 + b_k4off;
#pragma unroll
                for (int ma = 0; ma < 2; ma++) {
                    int rowm = mw + ma * 16 + a_row_in;
                    ldmatrix_x4(af[ma], sP + (uint32_t)(rowm * 512 + vc * 128
                                              + ((k4a ^ (rowm & 7)) << 4)));
                }
#pragma unroll
                for (int na = 0; na < 8; na++) {
                    int rown = nw2 + na * 8 + b_row_in;
                    ldmatrix_x2(bf[na], bV + (uint32_t)(rown * 128
                                              + ((k4b ^ (rown & 7)) << 4)));
                }
#pragma unroll
                for (int ma = 0; ma < 2; ma++)
#pragma unroll
                    for (int na = 0; na < 8; na++)
                        mma_tf32(acc2[ma][na], af[ma], bf[na]);
            }
            __syncthreads();
        }
    }

    // ---- epilogue: yout rows [b*4096 + m0 .. +64) ----
    const int rb = m0 + mw + (lane >> 2);
    const int cb = nw2 + (lane & 3) * 2;
#pragma unroll
    for (int ma = 0; ma < 2; ma++)
#pragma unroll
        for (int na = 0; na < 8; na++) {
            size_t r0 = (size_t)(b * 4096 + rb + ma * 16) * 256 + cb + na * 8;
            *(float2*)&Og[r0] = make_float2(acc2[ma][na][0], acc2[ma][na][1]);
            *(float2*)&Og[r0 + 8 * 256] = make_float2(acc2[ma][na][2], acc2[ma][na][3]);
        }
}

// ---------------------------------------------------------------------------
// Tensor-core tf32 GEMM (QKV projections): C = A·B^T, 128x128 tiles.
// ---------------------------------------------------------------------------
template <bool LEPI>
__global__ __launch_bounds__(256, 2)
void tc_gemm(const float* __restrict__ Ag, const float* __restrict__ Bg,
             float* __restrict__ Cg, int KD, int ldb, int ldc,
             long long sA, long long sB, long long sC, float scl)
{
    __shared__ __align__(16) float As[2][4096];
    __shared__ __align__(16) float Bs[2][4096];
    const uint32_t sA32 = smem_u32(As);
    const uint32_t sB32 = smem_u32(Bs);

    Ag += sA * (long long)blockIdx.z;
    Bg += sB * (long long)blockIdx.z;
    Cg += sC * (long long)blockIdx.z;

    const int tid = threadIdx.x;
    const int wid = tid >> 5;
    const int lane = tid & 31;
    const int m0 = blockIdx.x * 128;
    const int n0 = blockIdx.y * 128;
    const int mw = (wid & 1) * 64;
    const int nw = (wid >> 1) * 32;

    float acc[4][4][4];
#pragma unroll
    for (int i = 0; i < 4; i++)
#pragma unroll
        for (int j = 0; j < 4; j++)
#pragma unroll
            for (int e = 0; e < 4; e++) acc[i][j][e] = 0.f;

    const int cr = tid >> 3;
    const int ck4 = tid & 7;

    const int lj = lane >> 3;
    const int lr = lane & 7;
    const int a_row_in = lr + ((lj & 1) << 3);
    const int a_k4off = lj >> 1;
    const int b_row_in = lr;
    const int b_k4off = lj & 1;

    const int NIT = KD >> 5;

    {
#pragma unroll
        for (int i = 0; i < 4; i++) {
            int r = cr + 32 * i;
            uint32_t off = (uint32_t)((r * 32 + ((ck4 ^ (r & 7)) << 2)) * 4);
            cp_async16(sA32 + off, &Ag[(size_t)(m0 + r) * KD + 4 * ck4]);
            cp_async16(sB32 + off, &Bg[(size_t)(n0 + r) * ldb + 4 * ck4]);
        }
        cp_commit();
    }

    for (int it = 0; it < NIT; it++) {
        if (it + 1 < NIT) {
            const int k0 = (it + 1) << 5;
            const uint32_t bufo = (uint32_t)(((it + 1) & 1) * 16384);
#pragma unroll
            for (int i = 0; i < 4; i++) {
                int r = cr + 32 * i;
                uint32_t off = bufo + (uint32_t)((r * 32 + ((ck4 ^ (r & 7)) << 2)) * 4);
                cp_async16(sA32 + off, &Ag[(size_t)(m0 + r) * KD + k0 + 4 * ck4]);
                cp_async16(sB32 + off, &Bg[(size_t)(n0 + r) * ldb + k0 + 4 * ck4]);
            }
            cp_commit();
            cp_wait<1>();
        } else {
            cp_wait<0>();
        }
        __syncthreads();

        const uint32_t bA = sA32 + (uint32_t)((it & 1) * 16384);
        const uint32_t bB = sB32 + (uint32_t)((it & 1) * 16384);
#pragma unroll
        for (int ks = 0; ks < 4; ks++) {
            uint32_t af[4][4], bf[4][2];
#pragma unroll
            for (int ma = 0; ma < 4; ma++) {
                int rowm = mw + ma * 16 + a_row_in;
                int k4 = ks * 2 + a_k4off;
                ldmatrix_x4(af[ma], bA + (uint32_t)(rowm * 128 + ((k4 ^ (rowm & 7)) << 4)));
            }
#pragma unroll
            for (int na = 0; na < 4; na++) {
                int rown = nw + na * 8 + b_row_in;
                int k4 = ks * 2 + b_k4off;
                ldmatrix_x2(bf[na], bB + (uint32_t)(rown * 128 + ((k4 ^ (rown & 7)) << 4)));
            }
#pragma unroll
            for (int ma = 0; ma < 4; ma++)
#pragma unroll
                for (int na = 0; na < 4; na++)
                    mma_tf32(acc[ma][na], af[ma], bf[na]);
        }
        __syncthreads();
    }

    const int rbase = m0 + mw + (lane >> 2);
    const int cbase = n0 + nw + (lane & 3) * 2;
#pragma unroll
    for (int ma = 0; ma < 4; ma++)
#pragma unroll
        for (int na = 0; na < 4; na++) {
            float* d = acc[ma][na];
            float o[4];
#pragma unroll
            for (int e = 0; e < 4; e++) {
                float v = d[e] * scl;
                if (LEPI) { v = LEAKY(v); v = tf32r(v); }
                o[e] = v;
            }
            size_t r0 = (size_t)(rbase + ma * 16) * ldc + cbase + na * 8;
            *(float2*)&Cg[r0]                   = make_float2(o[0], o[1]);
            *(float2*)&Cg[r0 + (size_t)8 * ldc] = make_float2(o[2], o[3]);
        }
}

// tf32-round x into g_X (float4 per thread)
__global__ void round_x(const float* __restrict__ x)
{
    size_t i = (size_t)blockIdx.x * 256 + threadIdx.x;
    float4 v = ((const float4*)x)[i];
    v.x = tf32r(v.x); v.y = tf32r(v.y); v.z = tf32r(v.z); v.w = tf32r(v.w);
    ((float4*)g_X)[i] = v;
}

// transpose + tf32-round the three weight matrices: g_Wt[p][d][c] = W[c][d]
__global__ void prep_w(const float* __restrict__ Wq, const float* __restrict__ Wk,
                       const float* __restrict__ Wv)
{
    __shared__ float t[32][33];
    int p = blockIdx.z;
    const float* W = (p == 0) ? Wq : (p == 1) ? Wk : Wv;
    int c0 = blockIdx.x * 32, d0 = blockIdx.y * 32;
    int x = threadIdx.x, y = threadIdx.y;
#pragma unroll
    for (int r = 0; r < 4; r++)
        t[y + 8 * r][x] = W[(size_t)(c0 + y + 8 * r) * 256 + d0 + x];
    __syncthreads();
#pragma unroll
    for (int r = 0; r < 4; r++)
        g_Wt[(size_t)p * 65536 + (size_t)(d0 + y + 8 * r) * 256 + c0 + x] =
            tf32r(t[x][y + 8 * r]);
}

// V [b*4096+i][c] -> Vt [b][c][i]
__global__ void transpose_v(const float* __restrict__ V, float* __restrict__ Vt)
{
    __shared__ float t[32][33];
    int b = blockIdx.z;
    int i0 = blockIdx.x * 32;
    int c0 = blockIdx.y * 32;
    int x = threadIdx.x, y = threadIdx.y;
#pragma unroll
    for (int r = 0; r < 4; r++)
        t[y + 8 * r][x] = V[(size_t)(b * 4096 + i0 + y + 8 * r) * 256 + c0 + x];
    __syncthreads();
#pragma unroll
    for (int r = 0; r < 4; r++)
        Vt[(size_t)b * 1048576 + (size_t)(c0 + y + 8 * r) * 4096 + i0 + x] = t[x][y + 8 * r];
}

// Per-channel partial sums over 64-row chunks (deterministic, no atomics).
__global__ void stats_partial(const float* __restrict__ Y,
                              float* __restrict__ ps, float* __restrict__ pq)
{
    int proj = blockIdx.y;
    int c = threadIdx.x;
    const float* p = Y + (size_t)proj * PROJ_ELEMS + (size_t)blockIdx.x * 16384ull + c;
    float s = 0.f, s2 = 0.f;
#pragma unroll 8
    for (int r = 0; r < 64; r++) {
        float v = p[(size_t)r * 256];
        s += v;
        s2 = fmaf(v, v, s2);
    }
    int o = (proj * 256 + blockIdx.x) * 256 + c;
    ps[o] = s;
    pq[o] = s2;
}

__global__ void finalize_qkv(const float* gq, const float* bq,
                             const float* gk, const float* bk,
                             const float* gv, const float* bv)
{
    int proj = blockIdx.x;
    int c = threadIdx.x;
    float s = 0.f, s2 = 0.f;
    for (int i = 0; i < 256; i++) {
        int o = (proj * 256 + i) * 256 + c;
        s += g_ps[o];
        s2 += g_pq[o];
    }
    float mu = s * (1.f / 16384.f);
    float var = s2 * (1.f / 16384.f) - mu * mu;
    float rs = rsqrtf(var + 1e-3f);
    const float* g = (proj == 0) ? gq : (proj == 1) ? gk : gv;
    const float* b = (proj == 0) ? bq : (proj == 1) ? bk : bv;
    float sc = g[c] * rs;
    g_scale[proj * 256 + c] = sc;
    g_shift[proj * 256 + c] = b[c] - mu * sc;
}

__global__ void finalize_soft(const float* __restrict__ g1)
{
    int c = threadIdx.x;
    float s = 0.f, s2 = 0.f;
    for (int i = 0; i < 256; i++) {
        int o = i * 256 + c;
        s += g_ps2[o];
        s2 += g_pq2[o];
    }
    float mu = s * (1.f / 16384.f);
    float var = s2 * (1.f / 16384.f) - mu * mu;
    g_sscale[c] = g1[c] * rsqrtf(var + 1e-3f);
}

// In-place BN + LeakyReLU + round-to-tf32 (MMA operand conditioning).
__global__ void bnleaky_kern()
{
    size_t i4 = (size_t)blockIdx.x * 256 + threadIdx.x;
    int proj = (int)(i4 >> 20);
    int c4 = (int)(i4 & 63);
    float4 v = *(float4*)&g_Y[i4 * 4];
    int cb = proj * 256 + c4 * 4;
    float4 sc = *(float4*)&g_scale[cb];
    float4 sh = *(float4*)&g_shift[cb];
    v.x = fmaf(v.x, sc.x, sh.x); v.x = tf32r(LEAKY(v.x));
    v.y = fmaf(v.y, sc.y, sh.y); v.y = tf32r(LEAKY(v.y));
    v.z = fmaf(v.z, sc.z, sh.z); v.z = tf32r(LEAKY(v.z));
    v.w = fmaf(v.w, sc.w, sh.w); v.w = tf32r(LEAKY(v.w));
    *(float4*)&g_Y[i4 * 4] = v;
}

// Spatial softmax of s_c * yout per (batch, channel), over 4096 positions.
__global__ void softmax_kern(const float* __restrict__ yout, float* __restrict__ out)
{
    int b = blockIdx.y;
    int c = blockIdx.x * 8 + (threadIdx.x & 7);
    int il = threadIdx.x >> 3;
    float s = g_sscale[c];
    const float* base = yout + (size_t)b * 1048576ull + c;
    float* obase = out + (size_t)b * 1048576ull + c;
    __shared__ float red[256];

    float mx = -3.4e38f;
    for (int i = il; i < 4096; i += 32)
        mx = fmaxf(mx, s * base[(size_t)i * 256]);
    red[threadIdx.x] = mx;
    __syncthreads();
    for (int st = 128; st >= 8; st >>= 1) {
        if (threadIdx.x < st)
            red[threadIdx.x] = fmaxf(red[threadIdx.x], red[threadIdx.x + st]);
        __syncthreads();
    }
    mx = red[threadIdx.x & 7];
    __syncthreads();

    float sum = 0.f;
    for (int i = il; i < 4096; i += 32) {
        float e = expf(s * base[(size_t)i * 256] - mx);
        obase[(size_t)i * 256] = e;
        sum += e;
    }
    red[threadIdx.x] = sum;
    __syncthreads();
    for (int st = 128; st >= 8; st >>= 1) {
        if (threadIdx.x < st)
            red[threadIdx.x] += red[threadIdx.x + st];
        __syncthreads();
    }
    float inv = 1.f / red[threadIdx.x & 7];

    for (int i = il; i < 4096; i += 32)
        obase[(size_t)i * 256] *= inv;
}

// ---------------------------------------------------------------------------
extern "C" void kernel_launch(void* const* d_in, const int* in_sizes, int n_in,
                              void* d_out, int out_size)
{
    (void)in_sizes; (void)n_in; (void)out_size;
    const float* x  = (const float*)d_in[0];
    const float* Wq = (const float*)d_in[1];
    const float* gq = (const float*)d_in[2];
    const float* bq = (const float*)d_in[3];
    const float* Wk = (const float*)d_in[4];
    const float* gk = (const float*)d_in[5];
    const float* bk = (const float*)d_in[6];
    const float* Wv = (const float*)d_in[7];
    const float* gv = (const float*)d_in[8];
    const float* bv = (const float*)d_in[9];
    const float* g1 = (const float*)d_in[10];
    float* out = (float*)d_out;

    float *pX, *pWt, *pY, *pVt, *pyout, *pps, *ppq, *pps2, *ppq2;
    cudaGetSymbolAddress((void**)&pX, g_X);
    cudaGetSymbolAddress((void**)&pWt, g_Wt);
    cudaGetSymbolAddress((void**)&pY, g_Y);
    cudaGetSymbolAddress((void**)&pVt, g_Vt);
    cudaGetSymbolAddress((void**)&pyout, g_yout);
    cudaGetSymbolAddress((void**)&pps, g_ps);
    cudaGetSymbolAddress((void**)&ppq, g_pq);
    cudaGetSymbolAddress((void**)&pps2, g_ps2);
    cudaGetSymbolAddress((void**)&ppq2, g_pq2);

    const int FSMEM = 196608;
    cudaFuncSetAttribute(fused_attn,
                         cudaFuncAttributeMaxDynamicSharedMemorySize, FSMEM);

    // 0) condition operands: round x to tf32; transpose+round weights
    round_x<<<4096, 256>>>(x);
    prep_w<<<dim3(8, 8, 3), dim3(32, 8)>>>(Wq, Wk, Wv);

    // 1) QKV projections (pre-BN) on tensor cores: Y = X @ W  (B = W^T K-major)
    tc_gemm<false><<<dim3(128, 2, 1), 256>>>(pX, pWt, pY,
        256, 256, 256, 0, 0, 0, 1.f);
    tc_gemm<false><<<dim3(128, 2, 1), 256>>>(pX, pWt + 65536, pY + PROJ_ELEMS,
        256, 256, 256, 0, 0, 0, 1.f);
    tc_gemm<false><<<dim3(128, 2, 1), 256>>>(pX, pWt + 131072, pY + 2 * PROJ_ELEMS,
        256, 256, 256, 0, 0, 0, 1.f);

    // 2) BN stats + apply BN+leaky(+tf32 rounding) in place
    stats_partial<<<dim3(256, 3), 256>>>(pY, pps, ppq);
    finalize_qkv<<<3, 256>>>(gq, bq, gk, bk, gv, bv);
    bnleaky_kern<<<12288, 256>>>();

    // 3) V^T for K-major B loads in the fused kernel
    transpose_v<<<dim3(128, 8, 4), dim3(32, 8)>>>(pY + 2 * PROJ_ELEMS, pVt);

    // 4) fused: yout = leaky(Q K^T / 16) @ V   (no P in global memory)
    fused_attn<<<dim3(64, 1, 4), 256, FSMEM>>>(
        pY, pY + PROJ_ELEMS, pVt, pyout);

    // 5) variance of yout -> softmax temperature; spatial softmax
    stats_partial<<<dim3(256, 1), 256>>>(pyout, pps2, ppq2);
    finalize_soft<<<1, 256>>>(g1);
    softmax_kern<<<dim3(32, 4), 256>>>(pyout, out);
}

// round 15
// speedup vs baseline: 1.2475x; 1.2475x over previous
#include <cuda_runtime.h>
#include <math.h>
#include <cstdint>

// ---------------------------------------------------------------------------
// GroupAttentionLayer: B=4, H=W=64, C=256, RF=STRIDE=16 (windows tile exactly)
//   Q,K,V = leaky(BN(x @ W))                       [16384, 256] each
//   P     = leaky(Q K^T / 16)  per batch           [4096 x 4096]  (tf32 mma.sync)
//   yout  = P V                per batch           [4096 x 256]   (tf32 mma.sync)
//   out   = softmax_spatial( s_c * yout ),  s_c = g1_c * rsqrt(var_c(yout)+eps)
//   (BN shift cancels inside the spatial softmax)
// ---------------------------------------------------------------------------

#define PROJ_ELEMS 4194304ull      // 16384*256
#define QB_STRIDE  1048576ll       // 4096*256
#define PB_STRIDE  16777216ll      // 4096*4096

static __device__ __align__(16) float g_X[PROJ_ELEMS];          // tf32-rounded x
static __device__ __align__(16) float g_Wt[3ull * 65536ull];    // W^T, tf32-rounded
static __device__ __align__(16) float g_Y[3ull * PROJ_ELEMS];   // Q,K,V
static __device__ __align__(16) float g_Vt[4ull * 1048576ull];  // V^T [b][c][i]
static __device__ __align__(16) float g_P[4ull * 16777216ull];  // leaky scores
static __device__ __align__(16) float g_yout[PROJ_ELEMS];
static __device__ __align__(16) float g_ps[3 * 256 * 256];
static __device__ __align__(16) float g_pq[3 * 256 * 256];
static __device__ __align__(16) float g_ps2[256 * 256];
static __device__ __align__(16) float g_pq2[256 * 256];
static __device__ __align__(16) float g_scale[3 * 256];
static __device__ __align__(16) float g_shift[3 * 256];
static __device__ __align__(16) float g_sscale[256];

#define LEAKY(v) ((v) > 0.f ? (v) : 0.3f * (v))

__device__ __forceinline__ float tf32r(float x) {
    uint32_t u;
    asm("cvt.rna.tf32.f32 %0, %1;" : "=r"(u) : "f"(x));
    return __uint_as_float(u);
}

// mma.sync m16n8k8 tf32: D += A*B, row.col, fp32 accum.
__device__ __forceinline__ void mma_tf32(float* d, const uint32_t* a, const uint32_t* b)
{
    asm volatile(
        "mma.sync.aligned.m16n8k8.row.col.f32.tf32.tf32.f32 "
        "{%0,%1,%2,%3}, {%4,%5,%6,%7}, {%8,%9}, {%0,%1,%2,%3};\n"
        : "+f"(d[0]), "+f"(d[1]), "+f"(d[2]), "+f"(d[3])
        : "r"(a[0]), "r"(a[1]), "r"(a[2]), "r"(a[3]), "r"(b[0]), "r"(b[1]));
}

__device__ __forceinline__ void ldmatrix_x4(uint32_t* r, uint32_t addr)
{
    asm volatile("ldmatrix.sync.aligned.m8n8.x4.shared.b16 {%0,%1,%2,%3}, [%4];"
                 : "=r"(r[0]), "=r"(r[1]), "=r"(r[2]), "=r"(r[3]) : "r"(addr));
}
__device__ __forceinline__ void ldmatrix_x2(uint32_t* r, uint32_t addr)
{
    asm volatile("ldmatrix.sync.aligned.m8n8.x2.shared.b16 {%0,%1}, [%2];"
                 : "=r"(r[0]), "=r"(r[1]) : "r"(addr));
}

__device__ __forceinline__ uint32_t smem_u32(const void* p) {
    uint32_t a;
    asm("{ .reg .u64 t; cvta.to.shared.u64 t, %1; cvt.u32.u64 %0, t; }"
        : "=r"(a) : "l"(p));
    return a;
}

__device__ __forceinline__ void cp_async16(uint32_t saddr, const void* gptr)
{
    asm volatile("cp.async.cg.shared.global [%0], [%1], 16;\n"
                 :: "r"(saddr), "l"(gptr));
}
__device__ __forceinline__ void cp_commit()
{
    asm volatile("cp.async.commit_group;\n" ::: "memory");
}
template <int N>
__device__ __forceinline__ void cp_wait()
{
    asm volatile("cp.async.wait_group %0;\n" :: "n"(N) : "memory");
}

// ---------------------------------------------------------------------------
// Tensor-core tf32 GEMM: C[m0..+128, n0..+128] = epi(scl * A·B^T)
//   A: [M, KD] row-major.  B: [N, ldb] row-major, K contiguous (K-major).
// Block 128x128, K-chunk 32, 8 warps (2M x 4N), warp tile 64x32.
// 3-stage cp.async ring (96KB dynamic smem), ONE barrier per K-iter:
//   wait<=1 group -> sync -> issue it+2 -> compute it
// 16B-chunk XOR swizzle; fragments via ldmatrix (tf32-as-b16 trick).
// QKV3: B is the [768,256] concat W^T; C block writes to g_Y proj slab.
// ---------------------------------------------------------------------------
template <bool LEPI, bool QKV3>
__global__ __launch_bounds__(256, 2)
void tc_gemm(const float* __restrict__ Ag, const float* __restrict__ Bg,
             float* __restrict__ Cg, int KD, int ldb, int ldc,
             long long sA, long long sB, long long sC, float scl)
{
    extern __shared__ __align__(16) float dsm[];   // 3 * (16KB A + 16KB B)
    const uint32_t s0 = smem_u32(dsm);

    Ag += sA * (long long)blockIdx.z;
    Bg += sB * (long long)blockIdx.z;
    Cg += sC * (long long)blockIdx.z;

    const int tid = threadIdx.x;
    const int wid = tid >> 5;
    const int lane = tid & 31;
    const int m0 = blockIdx.x * 128;
    const int n0 = blockIdx.y * 128;
    int ncol = n0;
    if (QKV3) {
        int proj = n0 >> 8;
        Cg += (size_t)proj * PROJ_ELEMS;
        ncol = n0 & 255;
    }
    const int mw = (wid & 1) * 64;
    const int nw = (wid >> 1) * 32;

    float acc[4][4][4];
#pragma unroll
    for (int i = 0; i < 4; i++)
#pragma unroll
        for (int j = 0; j < 4; j++)
#pragma unroll
            for (int e = 0; e < 4; e++) acc[i][j][e] = 0.f;

    const int cr = tid >> 3;          // row base 0..31 (+32*i)
    const int ck4 = tid & 7;          // k4 chunk

    const int lj = lane >> 3;
    const int lr = lane & 7;
    const int a_row_in = lr + ((lj & 1) << 3);
    const int a_k4off = lj >> 1;
    const int b_row_in = lr;
    const int b_k4off = lj & 1;

    const int NIT = KD >> 5;

    // ---- prologue: stages 0 and 1 in flight ----
#pragma unroll
    for (int pg = 0; pg < 2; pg++) {
        const int k0 = pg << 5;
        const uint32_t sb = s0 + (uint32_t)(pg * 32768);
#pragma unroll
        for (int i = 0; i < 4; i++) {
            int r = cr + 32 * i;
            uint32_t off = (uint32_t)((r * 32 + ((ck4 ^ (r & 7)) << 2)) * 4);
            cp_async16(sb + off, &Ag[(size_t)(m0 + r) * KD + k0 + 4 * ck4]);
            cp_async16(sb + 16384 + off, &Bg[(size_t)(n0 + r) * ldb + k0 + 4 * ck4]);
        }
        cp_commit();
    }

    int st = 0;                        // stage of iteration it
    int stn = 2;                       // stage of iteration it+2
    for (int it = 0; it < NIT; it++) {
        if (it + 1 < NIT) cp_wait<1>(); else cp_wait<0>();
        __syncthreads();               // tile(it) visible; compute(it-1) retired

        if (it + 2 < NIT) {
            const int k0 = (it + 2) << 5;
            const uint32_t sb = s0 + (uint32_t)(stn * 32768);
#pragma unroll
            for (int i = 0; i < 4; i++) {
                int r = cr + 32 * i;
                uint32_t off = (uint32_t)((r * 32 + ((ck4 ^ (r & 7)) << 2)) * 4);
                cp_async16(sb + off, &Ag[(size_t)(m0 + r) * KD + k0 + 4 * ck4]);
                cp_async16(sb + 16384 + off, &Bg[(size_t)(n0 + r) * ldb + k0 + 4 * ck4]);
            }
            cp_commit();
        }

        const uint32_t bA = s0 + (uint32_t)(st * 32768);
        const uint32_t bB = bA + 16384;
#pragma unroll
        for (int ks = 0; ks < 4; ks++) {
            uint32_t af[4][4], bf[4][2];
#pragma unroll
            for (int ma = 0; ma < 4; ma++) {
                int rowm = mw + ma * 16 + a_row_in;
                int k4 = ks * 2 + a_k4off;
                ldmatrix_x4(af[ma], bA + (uint32_t)(rowm * 128 + ((k4 ^ (rowm & 7)) << 4)));
            }
#pragma unroll
            for (int na = 0; na < 4; na++) {
                int rown = nw + na * 8 + b_row_in;
                int k4 = ks * 2 + b_k4off;
                ldmatrix_x2(bf[na], bB + (uint32_t)(rown * 128 + ((k4 ^ (rown & 7)) << 4)));
            }
#pragma unroll
            for (int ma = 0; ma < 4; ma++)
#pragma unroll
                for (int na = 0; na < 4; na++)
                    mma_tf32(acc[ma][na], af[ma], bf[na]);
        }

        st = (st == 2) ? 0 : st + 1;
        stn = (stn == 2) ? 0 : stn + 1;
    }

    // ---- epilogue ----
    const int rbase = m0 + mw + (lane >> 2);
    const int cbase = ncol + nw + (lane & 3) * 2;
#pragma unroll
    for (int ma = 0; ma < 4; ma++)
#pragma unroll
        for (int na = 0; na < 4; na++) {
            float* d = acc[ma][na];
            float o[4];
#pragma unroll
            for (int e = 0; e < 4; e++) {
                float v = d[e] * scl;
                if (LEPI) { v = LEAKY(v); v = tf32r(v); }
                o[e] = v;
            }
            size_t r0 = (size_t)(rbase + ma * 16) * ldc + cbase + na * 8;
            *(float2*)&Cg[r0]                   = make_float2(o[0], o[1]);
            *(float2*)&Cg[r0 + (size_t)8 * ldc] = make_float2(o[2], o[3]);
        }
}

// tf32-round x into g_X (float4 per thread)
__global__ void round_x(const float* __restrict__ x)
{
    size_t i = (size_t)blockIdx.x * 256 + threadIdx.x;
    float4 v = ((const float4*)x)[i];
    v.x = tf32r(v.x); v.y = tf32r(v.y); v.z = tf32r(v.z); v.w = tf32r(v.w);
    ((float4*)g_X)[i] = v;
}

// transpose + tf32-round the three weight matrices: g_Wt[p][d][c] = W[c][d]
__global__ void prep_w(const float* __restrict__ Wq, const float* __restrict__ Wk,
                       const float* __restrict__ Wv)
{
    __shared__ float t[32][33];
    int p = blockIdx.z;
    const float* W = (p == 0) ? Wq : (p == 1) ? Wk : Wv;
    int c0 = blockIdx.x * 32, d0 = blockIdx.y * 32;
    int x = threadIdx.x, y = threadIdx.y;
#pragma unroll
    for (int r = 0; r < 4; r++)
        t[y + 8 * r][x] = W[(size_t)(c0 + y + 8 * r) * 256 + d0 + x];
    __syncthreads();
#pragma unroll
    for (int r = 0; r < 4; r++)
        g_Wt[(size_t)p * 65536 + (size_t)(d0 + y + 8 * r) * 256 + c0 + x] =
            tf32r(t[x][y + 8 * r]);
}

// V [b*4096+i][c] -> Vt [b][c][i]
__global__ void transpose_v(const float* __restrict__ V, float* __restrict__ Vt)
{
    __shared__ float t[32][33];
    int b = blockIdx.z;
    int i0 = blockIdx.x * 32;
    int c0 = blockIdx.y * 32;
    int x = threadIdx.x, y = threadIdx.y;
#pragma unroll
    for (int r = 0; r < 4; r++)
        t[y + 8 * r][x] = V[(size_t)(b * 4096 + i0 + y + 8 * r) * 256 + c0 + x];
    __syncthreads();
#pragma unroll
    for (int r = 0; r < 4; r++)
        Vt[(size_t)b * 1048576 + (size_t)(c0 + y + 8 * r) * 4096 + i0 + x] = t[x][y + 8 * r];
}

// Per-channel partial sums over 64-row chunks (deterministic, no atomics).
__global__ void stats_partial(const float* __restrict__ Y,
                              float* __restrict__ ps, float* __restrict__ pq)
{
    int proj = blockIdx.y;
    int c = threadIdx.x;
    const float* p = Y + (size_t)proj * PROJ_ELEMS + (size_t)blockIdx.x * 16384ull + c;
    float s = 0.f, s2 = 0.f;
#pragma unroll 8
    for (int r = 0; r < 64; r++) {
        float v = p[(size_t)r * 256];
        s += v;
        s2 = fmaf(v, v, s2);
    }
    int o = (proj * 256 + blockIdx.x) * 256 + c;
    ps[o] = s;
    pq[o] = s2;
}

__global__ void finalize_qkv(const float* gq, const float* bq,
                             const float* gk, const float* bk,
                             const float* gv, const float* bv)
{
    int proj = blockIdx.x;
    int c = threadIdx.x;
    float s = 0.f, s2 = 0.f;
    for (int i = 0; i < 256; i++) {
        int o = (proj * 256 + i) * 256 + c;
        s += g_ps[o];
        s2 += g_pq[o];
    }
    float mu = s * (1.f / 16384.f);
    float var = s2 * (1.f / 16384.f) - mu * mu;
    float rs = rsqrtf(var + 1e-3f);
    const float* g = (proj == 0) ? gq : (proj == 1) ? gk : gv;
    const float* b = (proj == 0) ? bq : (proj == 1) ? bk : bv;
    float sc = g[c] * rs;
    g_scale[proj * 256 + c] = sc;
    g_shift[proj * 256 + c] = b[c] - mu * sc;
}

__global__ void finalize_soft(const float* __restrict__ g1)
{
    int c = threadIdx.x;
    float s = 0.f, s2 = 0.f;
    for (int i = 0; i < 256; i++) {
        int o = i * 256 + c;
        s += g_ps2[o];
        s2 += g_pq2[o];
    }
    float mu = s * (1.f / 16384.f);
    float var = s2 * (1.f / 16384.f) - mu * mu;
    g_sscale[c] = g1[c] * rsqrtf(var + 1e-3f);
}

// In-place BN + LeakyReLU + round-to-tf32 (MMA operand conditioning).
__global__ void bnleaky_kern()
{
    size_t i4 = (size_t)blockIdx.x * 256 + threadIdx.x;
    int proj = (int)(i4 >> 20);
    int c4 = (int)(i4 & 63);
    float4 v = *(float4*)&g_Y[i4 * 4];
    int cb = proj * 256 + c4 * 4;
    float4 sc = *(float4*)&g_scale[cb];
    float4 sh = *(float4*)&g_shift[cb];
    v.x = fmaf(v.x, sc.x, sh.x); v.x = tf32r(LEAKY(v.x));
    v.y = fmaf(v.y, sc.y, sh.y); v.y = tf32r(LEAKY(v.y));
    v.z = fmaf(v.z, sc.z, sh.z); v.z = tf32r(LEAKY(v.z));
    v.w = fmaf(v.w, sc.w, sh.w); v.w = tf32r(LEAKY(v.w));
    *(float4*)&g_Y[i4 * 4] = v;
}

// Spatial softmax of s_c * yout per (batch, channel), over 4096 positions.
__global__ void softmax_kern(const float* __restrict__ yout, float* __restrict__ out)
{
    int b = blockIdx.y;
    int c = blockIdx.x * 8 + (threadIdx.x & 7);
    int il = threadIdx.x >> 3;
    float s = g_sscale[c];
    const float* base = yout + (size_t)b * 1048576ull + c;
    float* obase = out + (size_t)b * 1048576ull + c;
    __shared__ float red[256];

    float mx = -3.4e38f;
    for (int i = il; i < 4096; i += 32)
        mx = fmaxf(mx, s * base[(size_t)i * 256]);
    red[threadIdx.x] = mx;
    __syncthreads();
    for (int st = 128; st >= 8; st >>= 1) {
        if (threadIdx.x < st)
            red[threadIdx.x] = fmaxf(red[threadIdx.x], red[threadIdx.x + st]);
        __syncthreads();
    }
    mx = red[threadIdx.x & 7];
    __syncthreads();

    float sum = 0.f;
    for (int i = il; i < 4096; i += 32) {
        float e = expf(s * base[(size_t)i * 256] - mx);
        obase[(size_t)i * 256] = e;
        sum += e;
    }
    red[threadIdx.x] = sum;
    __syncthreads();
    for (int st = 128; st >= 8; st >>= 1) {
        if (threadIdx.x < st)
            red[threadIdx.x] += red[threadIdx.x + st];
        __syncthreads();
    }
    float inv = 1.f / red[threadIdx.x & 7];

    for (int i = il; i < 4096; i += 32)
        obase[(size_t)i * 256] *= inv;
}

// ---------------------------------------------------------------------------
extern "C" void kernel_launch(void* const* d_in, const int* in_sizes, int n_in,
                              void* d_out, int out_size)
{
    (void)in_sizes; (void)n_in; (void)out_size;
    const float* x  = (const float*)d_in[0];
    const float* Wq = (const float*)d_in[1];
    const float* gq = (const float*)d_in[2];
    const float* bq = (const float*)d_in[3];
    const float* Wk = (const float*)d_in[4];
    const float* gk = (const float*)d_in[5];
    const float* bk = (const float*)d_in[6];
    const float* Wv = (const float*)d_in[7];
    const float* gv = (const float*)d_in[8];
    const float* bv = (const float*)d_in[9];
    const float* g1 = (const float*)d_in[10];
    float* out = (float*)d_out;

    float *pX, *pWt, *pY, *pVt, *pP, *pyout, *pps, *ppq, *pps2, *ppq2;
    cudaGetSymbolAddress((void**)&pX, g_X);
    cudaGetSymbolAddress((void**)&pWt, g_Wt);
    cudaGetSymbolAddress((void**)&pY, g_Y);
    cudaGetSymbolAddress((void**)&pVt, g_Vt);
    cudaGetSymbolAddress((void**)&pP, g_P);
    cudaGetSymbolAddress((void**)&pyout, g_yout);
    cudaGetSymbolAddress((void**)&pps, g_ps);
    cudaGetSymbolAddress((void**)&ppq, g_pq);
    cudaGetSymbolAddress((void**)&pps2, g_ps2);
    cudaGetSymbolAddress((void**)&ppq2, g_pq2);

    const int GSMEM = 98304;   // 3-stage ring: 3 x (16KB A + 16KB B)
    cudaFuncSetAttribute(tc_gemm<false, true>,
                         cudaFuncAttributeMaxDynamicSharedMemorySize, GSMEM);
    cudaFuncSetAttribute(tc_gemm<true, false>,
                         cudaFuncAttributeMaxDynamicSharedMemorySize, GSMEM);
    cudaFuncSetAttribute(tc_gemm<false, false>,
                         cudaFuncAttributeMaxDynamicSharedMemorySize, GSMEM);

    // 0) condition operands: round x to tf32; transpose+round weights
    round_x<<<4096, 256>>>(x);
    prep_w<<<dim3(8, 8, 3), dim3(32, 8)>>>(Wq, Wk, Wv);

    // 1) QKV projections in ONE launch: B = g_Wt [768,256], proj from blockIdx.y
    tc_gemm<false, true><<<dim3(128, 6, 1), 256, GSMEM>>>(pX, pWt, pY,
        256, 256, 256, 0, 0, 0, 1.f);

    // 2) BN stats + apply BN+leaky(+tf32 rounding) in place
    stats_partial<<<dim3(256, 3), 256>>>(pY, pps, ppq);
    finalize_qkv<<<3, 256>>>(gq, bq, gk, bk, gv, bv);
    bnleaky_kern<<<12288, 256>>>();

    // 3) V^T for K-major B loads in the second big GEMM
    transpose_v<<<dim3(128, 8, 4), dim3(32, 8)>>>(pY + 2 * PROJ_ELEMS, pVt);

    // 4) P = leaky(Q K^T / 16)
    tc_gemm<true, false><<<dim3(32, 32, 4), 256, GSMEM>>>(
        pY, pY + PROJ_ELEMS, pP,
        256, 256, 4096, QB_STRIDE, QB_STRIDE, PB_STRIDE, 0.0625f);

    // 5) yout = P @ V  (B = Vt K-major)
    tc_gemm<false, false><<<dim3(32, 2, 4), 256, GSMEM>>>(
        pP, pVt, pyout,
        4096, 4096, 256, PB_STRIDE, QB_STRIDE, QB_STRIDE, 1.f);

    // 6) variance of yout -> softmax temperature; spatial softmax
    stats_partial<<<dim3(256, 1), 256>>>(pyout, pps2, ppq2);
    finalize_soft<<<1, 256>>>(g1);
    softmax_kern<<<dim3(32, 4), 256>>>(pyout, out);
}

// round 16
// speedup vs baseline: 2.0020x; 1.6049x over previous
#include <cuda_runtime.h>
#include <cuda_fp16.h>
#include <math.h>
#include <cstdint>

// ---------------------------------------------------------------------------
// GroupAttentionLayer: B=4, H=W=64, C=256, RF=STRIDE=16 (windows tile exactly)
//   Q,K,V = leaky(BN(x @ W))                       [16384, 256] each
//   P     = leaky(Q K^T / 16)  per batch           [4096 x 4096]  (fp16 mma, fp32 acc)
//   yout  = P V                per batch           [4096 x 256]   (fp16 mma, fp32 acc)
//   out   = softmax_spatial( s_c * yout ),  s_c = g1_c * rsqrt(var_c(yout)+eps)
//   (BN shift cancels inside the spatial softmax)
// fp16 operands carry an 11-bit mantissa == tf32; all values are O(1..30),
// so precision matches the previous tf32 path (rel_err ~4.4e-4 < 1e-3).
// ---------------------------------------------------------------------------

#define PROJ_ELEMS 4194304ull      // 16384*256
#define QB_STRIDE  1048576ll       // 4096*256
#define PB_STRIDE  16777216ll      // 4096*4096

static __device__ __align__(16) __half g_Xh[PROJ_ELEMS];         // fp16 x
static __device__ __align__(16) __half g_Wth[3ull * 65536ull];   // W^T fp16
static __device__ __align__(16) float  g_Y[3ull * PROJ_ELEMS];   // pre-BN QKV fp32
static __device__ __align__(16) __half g_H[3ull * PROJ_ELEMS];   // post-BN QKV fp16
static __device__ __align__(16) __half g_Vth[4ull * 1048576ull]; // V^T fp16 [b][c][i]
static __device__ __align__(16) __half g_Ph[4ull * 16777216ull]; // leaky scores fp16
static __device__ __align__(16) float  g_yout[PROJ_ELEMS];
static __device__ __align__(16) float  g_ps[3 * 256 * 256];
static __device__ __align__(16) float  g_pq[3 * 256 * 256];
static __device__ __align__(16) float  g_ps2[256 * 256];
static __device__ __align__(16) float  g_pq2[256 * 256];
static __device__ __align__(16) float  g_scale[3 * 256];
static __device__ __align__(16) float  g_shift[3 * 256];
static __device__ __align__(16) float  g_sscale[256];

#define LEAKY(v) ((v) > 0.f ? (v) : 0.3f * (v))

// mma.sync m16n8k16 fp16 inputs, fp32 accum. (sm_80+, valid on sm_103 family)
__device__ __forceinline__ void mma_f16(float* d, const uint32_t* a, const uint32_t* b)
{
    asm volatile(
        "mma.sync.aligned.m16n8k16.row.col.f32.f16.f16.f32 "
        "{%0,%1,%2,%3}, {%4,%5,%6,%7}, {%8,%9}, {%0,%1,%2,%3};\n"
        : "+f"(d[0]), "+f"(d[1]), "+f"(d[2]), "+f"(d[3])
        : "r"(a[0]), "r"(a[1]), "r"(a[2]), "r"(a[3]), "r"(b[0]), "r"(b[1]));
}

__device__ __forceinline__ void ldmatrix_x4(uint32_t* r, uint32_t addr)
{
    asm volatile("ldmatrix.sync.aligned.m8n8.x4.shared.b16 {%0,%1,%2,%3}, [%4];"
                 : "=r"(r[0]), "=r"(r[1]), "=r"(r[2]), "=r"(r[3]) : "r"(addr));
}
__device__ __forceinline__ void ldmatrix_x2(uint32_t* r, uint32_t addr)
{
    asm volatile("ldmatrix.sync.aligned.m8n8.x2.shared.b16 {%0,%1}, [%2];"
                 : "=r"(r[0]), "=r"(r[1]) : "r"(addr));
}

__device__ __forceinline__ uint32_t smem_u32(const void* p) {
    uint32_t a;
    asm("{ .reg .u64 t; cvta.to.shared.u64 t, %1; cvt.u32.u64 %0, t; }"
        : "=r"(a) : "l"(p));
    return a;
}

__device__ __forceinline__ void cp_async16(uint32_t saddr, const void* gptr)
{
    asm volatile("cp.async.cg.shared.global [%0], [%1], 16;\n"
                 :: "r"(saddr), "l"(gptr));
}
__device__ __forceinline__ void cp_commit()
{
    asm volatile("cp.async.commit_group;\n" ::: "memory");
}
template <int N>
__device__ __forceinline__ void cp_wait()
{
    asm volatile("cp.async.wait_group %0;\n" :: "n"(N) : "memory");
}

// ---------------------------------------------------------------------------
// fp16 tensor-core GEMM: C[m0..+128, n0..+128] = epi(scl * A·B^T)
//   A: [M, KD] half row-major.  B: [N, ldb] half row-major, K contiguous.
// Block 128x128, K-chunk 64, 8 warps (2M x 4N), warp tile 64x32.
// 3-stage cp.async ring (96KB smem), one barrier per K-iter.
// SMEM tile: 128 rows x 64 halves (128B rows); 16B-chunk XOR swizzle:
//   chunk (r, c8) at byte r*128 + ((c8 ^ (r&7))*16)
// OUTH: C is half (P). QKV3: B = [768,256] concat W^T, C slab by proj.
// ---------------------------------------------------------------------------
template <bool LEPI, bool QKV3, bool OUTH>
__global__ __launch_bounds__(256, 2)
void tc_gemm(const __half* __restrict__ Ag, const __half* __restrict__ Bg,
             void* __restrict__ Cv, int KD, int ldb, int ldc,
             long long sA, long long sB, long long sC, float scl)
{
    extern __shared__ __align__(16) char dsm[];   // 3 * (16KB A + 16KB B)
    const uint32_t s0 = smem_u32(dsm);

    Ag += sA * (long long)blockIdx.z;
    Bg += sB * (long long)blockIdx.z;
    float* Cf = (float*)Cv;
    __half* Ch = (__half*)Cv;
    if (OUTH) Ch += sC * (long long)blockIdx.z;
    else      Cf += sC * (long long)blockIdx.z;

    const int tid = threadIdx.x;
    const int wid = tid >> 5;
    const int lane = tid & 31;
    const int m0 = blockIdx.x * 128;
    const int n0 = blockIdx.y * 128;
    int ncol = n0;
    if (QKV3) {
        int proj = n0 >> 8;
        Cf += (size_t)proj * PROJ_ELEMS;
        ncol = n0 & 255;
    }
    const int mw = (wid & 1) * 64;
    const int nw = (wid >> 1) * 32;

    float acc[4][4][4];
#pragma unroll
    for (int i = 0; i < 4; i++)
#pragma unroll
        for (int j = 0; j < 4; j++)
#pragma unroll
            for (int e = 0; e < 4; e++) acc[i][j][e] = 0.f;

    const int cr = tid >> 3;          // row base 0..31 (+32*i)
    const int ck8 = tid & 7;          // 16B (8-half) chunk

    const int lj = lane >> 3;
    const int lr = lane & 7;
    const int a_row_in = lr + ((lj & 1) << 3);
    const int a_k8off = lj >> 1;      // chunk offset within kstep pair
    const int b_row_in = lr;
    const int b_k8off = lj & 1;

    const int NIT = KD >> 6;          // K-chunk = 64

    // ---- prologue: stages 0 and 1 in flight ----
#pragma unroll
    for (int pg = 0; pg < 2; pg++) {
        if (pg >= NIT) break;
        const int k0 = pg << 6;
        const uint32_t sb = s0 + (uint32_t)(pg * 32768);
#pragma unroll
        for (int i = 0; i < 4; i++) {
            int r = cr + 32 * i;
            uint32_t off = (uint32_t)(r * 128 + ((ck8 ^ (r & 7)) << 4));
            cp_async16(sb + off, &Ag[(size_t)(m0 + r) * KD + k0 + 8 * ck8]);
            cp_async16(sb + 16384 + off, &Bg[(size_t)(n0 + r) * ldb + k0 + 8 * ck8]);
        }
        cp_commit();
    }

    int st = 0, stn = 2;
    for (int it = 0; it < NIT; it++) {
        if (it + 1 < NIT) cp_wait<1>(); else cp_wait<0>();
        __syncthreads();               // tile(it) visible; compute(it-1) retired

        if (it + 2 < NIT) {
            const int k0 = (it + 2) << 6;
            const uint32_t sb = s0 + (uint32_t)(stn * 32768);
#pragma unroll
            for (int i = 0; i < 4; i++) {
                int r = cr + 32 * i;
                uint32_t off = (uint32_t)(r * 128 + ((ck8 ^ (r & 7)) << 4));
                cp_async16(sb + off, &Ag[(size_t)(m0 + r) * KD + k0 + 8 * ck8]);
                cp_async16(sb + 16384 + off, &Bg[(size_t)(n0 + r) * ldb + k0 + 8 * ck8]);
            }
            cp_commit();
        }

        const uint32_t bA = s0 + (uint32_t)(st * 32768);
        const uint32_t bB = bA + 16384;
        // 4 ksteps of k16 per 64-deep chunk
#pragma unroll
        for (int ks = 0; ks < 4; ks++) {
            uint32_t af[4][4], bf[4][2];
#pragma unroll
            for (int ma = 0; ma < 4; ma++) {
                int rowm = mw + ma * 16 + a_row_in;
                int c8 = ks * 2 + a_k8off;
                ldmatrix_x4(af[ma], bA + (uint32_t)(rowm * 128 + ((c8 ^ (rowm & 7)) << 4)));
            }
#pragma unroll
            for (int na = 0; na < 4; na++) {
                int rown = nw + na * 8 + b_row_in;
                int c8 = ks * 2 + b_k8off;
                ldmatrix_x2(bf[na], bB + (uint32_t)(rown * 128 + ((c8 ^ (rown & 7)) << 4)));
            }
#pragma unroll
            for (int ma = 0; ma < 4; ma++)
#pragma unroll
                for (int na = 0; na < 4; na++)
                    mma_f16(acc[ma][na], af[ma], bf[na]);
        }

        st = (st == 2) ? 0 : st + 1;
        stn = (stn == 2) ? 0 : stn + 1;
    }

    // ---- epilogue ----
    const int rbase = m0 + mw + (lane >> 2);
    const int cbase = ncol + nw + (lane & 3) * 2;
#pragma unroll
    for (int ma = 0; ma < 4; ma++)
#pragma unroll
        for (int na = 0; na < 4; na++) {
            float* d = acc[ma][na];
            float o[4];
#pragma unroll
            for (int e = 0; e < 4; e++) {
                float v = d[e] * scl;
                if (LEPI) v = LEAKY(v);
                o[e] = v;
            }
            size_t r0 = (size_t)(rbase + ma * 16) * ldc + cbase + na * 8;
            if (OUTH) {
                *(__half2*)&Ch[r0] = __floats2half2_rn(o[0], o[1]);
                *(__half2*)&Ch[r0 + (size_t)8 * ldc] = __floats2half2_rn(o[2], o[3]);
            } else {
                *(float2*)&Cf[r0]                   = make_float2(o[0], o[1]);
                *(float2*)&Cf[r0 + (size_t)8 * ldc] = make_float2(o[2], o[3]);
            }
        }
}

// x -> fp16 (4 elems/thread)
__global__ void prep_x(const float* __restrict__ x)
{
    size_t i = (size_t)blockIdx.x * 256 + threadIdx.x;
    float4 v = ((const float4*)x)[i];
    __half2* dst = (__half2*)&g_Xh[i * 4];
    dst[0] = __floats2half2_rn(v.x, v.y);
    dst[1] = __floats2half2_rn(v.z, v.w);
}

// transpose + fp16-round weights: g_Wth[p][d][c] = W[c][d]
__global__ void prep_w(const float* __restrict__ Wq, const float* __restrict__ Wk,
                       const float* __restrict__ Wv)
{
    __shared__ float t[32][33];
    int p = blockIdx.z;
    const float* W = (p == 0) ? Wq : (p == 1) ? Wk : Wv;
    int c0 = blockIdx.x * 32, d0 = blockIdx.y * 32;
    int x = threadIdx.x, y = threadIdx.y;
#pragma unroll
    for (int r = 0; r < 4; r++)
        t[y + 8 * r][x] = W[(size_t)(c0 + y + 8 * r) * 256 + d0 + x];
    __syncthreads();
#pragma unroll
    for (int r = 0; r < 4; r++)
        g_Wth[(size_t)p * 65536 + (size_t)(d0 + y + 8 * r) * 256 + c0 + x] =
            __float2half_rn(t[x][y + 8 * r]);
}

// V half [b*4096+i][c] -> Vt half [b][c][i]
__global__ void transpose_v(const __half* __restrict__ V, __half* __restrict__ Vt)
{
    __shared__ __half t[32][40];
    int b = blockIdx.z;
    int i0 = blockIdx.x * 32;
    int c0 = blockIdx.y * 32;
    int x = threadIdx.x, y = threadIdx.y;
#pragma unroll
    for (int r = 0; r < 4; r++)
        t[y + 8 * r][x] = V[(size_t)(b * 4096 + i0 + y + 8 * r) * 256 + c0 + x];
    __syncthreads();
#pragma unroll
    for (int r = 0; r < 4; r++)
        Vt[(size_t)b * 1048576 + (size_t)(c0 + y + 8 * r) * 4096 + i0 + x] = t[x][y + 8 * r];
}

// Per-channel partial sums over 64-row chunks (deterministic, no atomics).
__global__ void stats_partial(const float* __restrict__ Y,
                              float* __restrict__ ps, float* __restrict__ pq)
{
    int proj = blockIdx.y;
    int c = threadIdx.x;
    const float* p = Y + (size_t)proj * PROJ_ELEMS + (size_t)blockIdx.x * 16384ull + c;
    float s = 0.f, s2 = 0.f;
#pragma unroll 8
    for (int r = 0; r < 64; r++) {
        float v = p[(size_t)r * 256];
        s += v;
        s2 = fmaf(v, v, s2);
    }
    int o = (proj * 256 + blockIdx.x) * 256 + c;
    ps[o] = s;
    pq[o] = s2;
}

__global__ void finalize_qkv(const float* gq, const float* bq,
                             const float* gk, const float* bk,
                             const float* gv, const float* bv)
{
    int proj = blockIdx.x;
    int c = threadIdx.x;
    float s = 0.f, s2 = 0.f;
    for (int i = 0; i < 256; i++) {
        int o = (proj * 256 + i) * 256 + c;
        s += g_ps[o];
        s2 += g_pq[o];
    }
    float mu = s * (1.f / 16384.f);
    float var = s2 * (1.f / 16384.f) - mu * mu;
    float rs = rsqrtf(var + 1e-3f);
    const float* g = (proj == 0) ? gq : (proj == 1) ? gk : gv;
    const float* b = (proj == 0) ? bq : (proj == 1) ? bk : bv;
    float sc = g[c] * rs;
    g_scale[proj * 256 + c] = sc;
    g_shift[proj * 256 + c] = b[c] - mu * sc;
}

__global__ void finalize_soft(const float* __restrict__ g1)
{
    int c = threadIdx.x;
    float s = 0.f, s2 = 0.f;
    for (int i = 0; i < 256; i++) {
        int o = i * 256 + c;
        s += g_ps2[o];
        s2 += g_pq2[o];
    }
    float mu = s * (1.f / 16384.f);
    float var = s2 * (1.f / 16384.f) - mu * mu;
    g_sscale[c] = g1[c] * rsqrtf(var + 1e-3f);
}

// BN + LeakyReLU + fp16 round: g_Y (fp32) -> g_H (fp16)
__global__ void bnleaky_kern()
{
    size_t i4 = (size_t)blockIdx.x * 256 + threadIdx.x;
    int proj = (int)(i4 >> 20);
    int c4 = (int)(i4 & 63);
    float4 v = *(float4*)&g_Y[i4 * 4];
    int cb = proj * 256 + c4 * 4;
    float4 sc = *(float4*)&g_scale[cb];
    float4 sh = *(float4*)&g_shift[cb];
    v.x = fmaf(v.x, sc.x, sh.x); v.x = LEAKY(v.x);
    v.y = fmaf(v.y, sc.y, sh.y); v.y = LEAKY(v.y);
    v.z = fmaf(v.z, sc.z, sh.z); v.z = LEAKY(v.z);
    v.w = fmaf(v.w, sc.w, sh.w); v.w = LEAKY(v.w);
    __half2* dst = (__half2*)&g_H[i4 * 4];
    dst[0] = __floats2half2_rn(v.x, v.y);
    dst[1] = __floats2half2_rn(v.z, v.w);
}

// Spatial softmax of s_c * yout per (batch, channel), over 4096 positions.
__global__ void softmax_kern(const float* __restrict__ yout, float* __restrict__ out)
{
    int b = blockIdx.y;
    int c = blockIdx.x * 8 + (threadIdx.x & 7);
    int il = threadIdx.x >> 3;
    float s = g_sscale[c];
    const float* base = yout + (size_t)b * 1048576ull + c;
    float* obase = out + (size_t)b * 1048576ull + c;
    __shared__ float red[256];

    float mx = -3.4e38f;
    for (int i = il; i < 4096; i += 32)
        mx = fmaxf(mx, s * base[(size_t)i * 256]);
    red[threadIdx.x] = mx;
    __syncthreads();
    for (int st = 128; st >= 8; st >>= 1) {
        if (threadIdx.x < st)
            red[threadIdx.x] = fmaxf(red[threadIdx.x], red[threadIdx.x + st]);
        __syncthreads();
    }
    mx = red[threadIdx.x & 7];
    __syncthreads();

    float sum = 0.f;
    for (int i = il; i < 4096; i += 32) {
        float e = expf(s * base[(size_t)i * 256] - mx);
        obase[(size_t)i * 256] = e;
        sum += e;
    }
    red[threadIdx.x] = sum;
    __syncthreads();
    for (int st = 128; st >= 8; st >>= 1) {
        if (threadIdx.x < st)
            red[threadIdx.x] += red[threadIdx.x + st];
        __syncthreads();
    }
    float inv = 1.f / red[threadIdx.x & 7];

    for (int i = il; i < 4096; i += 32)
        obase[(size_t)i * 256] *= inv;
}

// ---------------------------------------------------------------------------
extern "C" void kernel_launch(void* const* d_in, const int* in_sizes, int n_in,
                              void* d_out, int out_size)
{
    (void)in_sizes; (void)n_in; (void)out_size;
    const float* x  = (const float*)d_in[0];
    const float* Wq = (const float*)d_in[1];
    const float* gq = (const float*)d_in[2];
    const float* bq = (const float*)d_in[3];
    const float* Wk = (const float*)d_in[4];
    const float* gk = (const float*)d_in[5];
    const float* bk = (const float*)d_in[6];
    const float* Wv = (const float*)d_in[7];
    const float* gv = (const float*)d_in[8];
    const float* bv = (const float*)d_in[9];
    const float* g1 = (const float*)d_in[10];
    float* out = (float*)d_out;

    __half *pXh, *pWth, *pH, *pVth, *pPh;
    float *pY, *pyout, *pps, *ppq, *pps2, *ppq2;
    cudaGetSymbolAddress((void**)&pXh, g_Xh);
    cudaGetSymbolAddress((void**)&pWth, g_Wth);
    cudaGetSymbolAddress((void**)&pY, g_Y);
    cudaGetSymbolAddress((void**)&pH, g_H);
    cudaGetSymbolAddress((void**)&pVth, g_Vth);
    cudaGetSymbolAddress((void**)&pPh, g_Ph);
    cudaGetSymbolAddress((void**)&pyout, g_yout);
    cudaGetSymbolAddress((void**)&pps, g_ps);
    cudaGetSymbolAddress((void**)&ppq, g_pq);
    cudaGetSymbolAddress((void**)&pps2, g_ps2);
    cudaGetSymbolAddress((void**)&ppq2, g_pq2);

    const int GSMEM = 98304;   // 3-stage ring: 3 x (16KB A + 16KB B)
    cudaFuncSetAttribute(tc_gemm<false, true, false>,
                         cudaFuncAttributeMaxDynamicSharedMemorySize, GSMEM);
    cudaFuncSetAttribute(tc_gemm<true, false, true>,
                         cudaFuncAttributeMaxDynamicSharedMemorySize, GSMEM);
    cudaFuncSetAttribute(tc_gemm<false, false, false>,
                         cudaFuncAttributeMaxDynamicSharedMemorySize, GSMEM);

    // 0) condition operands to fp16
    prep_x<<<4096, 256>>>(x);
    prep_w<<<dim3(8, 8, 3), dim3(32, 8)>>>(Wq, Wk, Wv);

    // 1) QKV projections in ONE launch (fp16 in, fp32 out pre-BN)
    tc_gemm<false, true, false><<<dim3(128, 6, 1), 256, GSMEM>>>(
        pXh, pWth, pY, 256, 256, 256, 0, 0, 0, 1.f);

    // 2) BN stats + apply BN+leaky -> fp16 Q,K,V
    stats_partial<<<dim3(256, 3), 256>>>(pY, pps, ppq);
    finalize_qkv<<<3, 256>>>(gq, bq, gk, bk, gv, bv);
    bnleaky_kern<<<12288, 256>>>();

    // 3) V^T (fp16) for K-major B loads in GEMM2
    transpose_v<<<dim3(128, 8, 4), dim3(32, 8)>>>(pH + 2 * PROJ_ELEMS, pVth);

    // 4) P = leaky(Q K^T / 16)  -> fp16
    tc_gemm<true, false, true><<<dim3(32, 32, 4), 256, GSMEM>>>(
        pH, pH + PROJ_ELEMS, pPh,
        256, 256, 4096, QB_STRIDE, QB_STRIDE, PB_STRIDE, 0.0625f);

    // 5) yout = P @ V  (fp16 in, fp32 out)
    tc_gemm<false, false, false><<<dim3(32, 2, 4), 256, GSMEM>>>(
        pPh, pVth, pyout,
        4096, 4096, 256, PB_STRIDE, QB_STRIDE, QB_STRIDE, 1.f);

    // 6) variance of yout -> softmax temperature; spatial softmax
    stats_partial<<<dim3(256, 1), 256>>>(pyout, pps2, ppq2);
    finalize_soft<<<1, 256>>>(g1);
    softmax_kern<<<dim3(32, 4), 256>>>(pyout, out);
}

// round 17
// speedup vs baseline: 2.0866x; 1.0422x over previous
#include <cuda_runtime.h>
#include <cuda_fp16.h>
#include <math.h>
#include <cstdint>

// ---------------------------------------------------------------------------
// GroupAttentionLayer: B=4, H=W=64, C=256, RF=STRIDE=16 (windows tile exactly)
//   Q,K,V = leaky(BN(x @ W))                       [16384, 256] each
//   P     = leaky(Q K^T / 16)  per batch           [4096 x 4096]  (fp16 mma, fp32 acc)
//   yout  = P V                per batch           [4096 x 256]   (fp16 mma, fp32 acc)
//   out   = softmax_spatial( s_c * yout ),  s_c = g1_c * rsqrt(var_c(yout)+eps)
//   (BN shift cancels inside the spatial softmax)
// BN / softmax variance stats are computed INSIDE the GEMM epilogues
// (deterministic shfl+smem reduction of the fp32 accumulators).
// ---------------------------------------------------------------------------

#define PROJ_ELEMS 4194304ull      // 16384*256
#define QB_STRIDE  1048576ll       // 4096*256
#define PB_STRIDE  16777216ll      // 4096*4096

static __device__ __align__(16) __half g_Xh[PROJ_ELEMS];         // fp16 x
static __device__ __align__(16) __half g_Wth[3ull * 65536ull];   // W^T fp16
static __device__ __align__(16) float  g_Y[3ull * PROJ_ELEMS];   // pre-BN QKV fp32
static __device__ __align__(16) __half g_H[3ull * PROJ_ELEMS];   // post-BN QKV fp16
static __device__ __align__(16) __half g_Vth[4ull * 1048576ull]; // V^T fp16 [b][c][i]
static __device__ __align__(16) __half g_Ph[4ull * 16777216ull]; // leaky scores fp16
static __device__ __align__(16) float  g_yout[PROJ_ELEMS];
static __device__ __align__(16) float  g_ps[128 * 768];
static __device__ __align__(16) float  g_pq[128 * 768];
static __device__ __align__(16) float  g_ps2[128 * 256];
static __device__ __align__(16) float  g_pq2[128 * 256];
static __device__ __align__(16) float  g_scale[3 * 256];
static __device__ __align__(16) float  g_shift[3 * 256];
static __device__ __align__(16) float  g_sscale[256];

#define LEAKY(v) ((v) > 0.f ? (v) : 0.3f * (v))

// mma.sync m16n8k16 fp16 inputs, fp32 accum.
__device__ __forceinline__ void mma_f16(float* d, const uint32_t* a, const uint32_t* b)
{
    asm volatile(
        "mma.sync.aligned.m16n8k16.row.col.f32.f16.f16.f32 "
        "{%0,%1,%2,%3}, {%4,%5,%6,%7}, {%8,%9}, {%0,%1,%2,%3};\n"
        : "+f"(d[0]), "+f"(d[1]), "+f"(d[2]), "+f"(d[3])
        : "r"(a[0]), "r"(a[1]), "r"(a[2]), "r"(a[3]), "r"(b[0]), "r"(b[1]));
}

__device__ __forceinline__ void ldmatrix_x4(uint32_t* r, uint32_t addr)
{
    asm volatile("ldmatrix.sync.aligned.m8n8.x4.shared.b16 {%0,%1,%2,%3}, [%4];"
                 : "=r"(r[0]), "=r"(r[1]), "=r"(r[2]), "=r"(r[3]) : "r"(addr));
}
__device__ __forceinline__ void ldmatrix_x2(uint32_t* r, uint32_t addr)
{
    asm volatile("ldmatrix.sync.aligned.m8n8.x2.shared.b16 {%0,%1}, [%2];"
                 : "=r"(r[0]), "=r"(r[1]) : "r"(addr));
}

__device__ __forceinline__ uint32_t smem_u32(const void* p) {
    uint32_t a;
    asm("{ .reg .u64 t; cvta.to.shared.u64 t, %1; cvt.u32.u64 %0, t; }"
        : "=r"(a) : "l"(p));
    return a;
}

__device__ __forceinline__ void cp_async16(uint32_t saddr, const void* gptr)
{
    asm volatile("cp.async.cg.shared.global [%0], [%1], 16;\n"
                 :: "r"(saddr), "l"(gptr));
}
__device__ __forceinline__ void cp_commit()
{
    asm volatile("cp.async.commit_group;\n" ::: "memory");
}
template <int N>
__device__ __forceinline__ void cp_wait()
{
    asm volatile("cp.async.wait_group %0;\n" :: "n"(N) : "memory");
}

// ---------------------------------------------------------------------------
// fp16 tensor-core GEMM: C[m0..+128, n0..+128] = epi(scl * A·B^T)
// Block 128x128, K-chunk 64, 8 warps (2M x 4N), warp tile 64x32.
// 3-stage cp.async ring (96KB smem), one barrier per K-iter.
// STATS: epilogue also writes per-block per-channel (sum, sumsq) of the
//   fp32 outputs to ps/pq at slot = bx + gridDim.x*bz, width = gridDim.y*128.
// ---------------------------------------------------------------------------
template <bool LEPI, bool QKV3, bool OUTH, bool STATS>
__global__ __launch_bounds__(256, 2)
void tc_gemm(const __half* __restrict__ Ag, const __half* __restrict__ Bg,
             void* __restrict__ Cv, int KD, int ldb, int ldc,
             long long sA, long long sB, long long sC, float scl,
             float* __restrict__ ps, float* __restrict__ pq)
{
    extern __shared__ __align__(16) char dsm[];   // 3 * (16KB A + 16KB B)
    const uint32_t s0 = smem_u32(dsm);

    Ag += sA * (long long)blockIdx.z;
    Bg += sB * (long long)blockIdx.z;
    float* Cf = (float*)Cv;
    __half* Ch = (__half*)Cv;
    if (OUTH) Ch += sC * (long long)blockIdx.z;
    else      Cf += sC * (long long)blockIdx.z;

    const int tid = threadIdx.x;
    const int wid = tid >> 5;
    const int lane = tid & 31;
    const int m0 = blockIdx.x * 128;
    const int n0 = blockIdx.y * 128;
    int ncol = n0;
    if (QKV3) {
        int proj = n0 >> 8;
        Cf += (size_t)proj * PROJ_ELEMS;
        ncol = n0 & 255;
    }
    const int mw = (wid & 1) * 64;
    const int nw = (wid >> 1) * 32;

    float acc[4][4][4];
#pragma unroll
    for (int i = 0; i < 4; i++)
#pragma unroll
        for (int j = 0; j < 4; j++)
#pragma unroll
            for (int e = 0; e < 4; e++) acc[i][j][e] = 0.f;

    const int cr = tid >> 3;          // row base 0..31 (+32*i)
    const int ck8 = tid & 7;          // 16B (8-half) chunk

    const int lj = lane >> 3;
    const int lr = lane & 7;
    const int a_row_in = lr + ((lj & 1) << 3);
    const int a_k8off = lj >> 1;
    const int b_row_in = lr;
    const int b_k8off = lj & 1;

    const int NIT = KD >> 6;          // K-chunk = 64

#pragma unroll
    for (int pg = 0; pg < 2; pg++) {
        if (pg >= NIT) break;
        const int k0 = pg << 6;
        const uint32_t sb = s0 + (uint32_t)(pg * 32768);
#pragma unroll
        for (int i = 0; i < 4; i++) {
            int r = cr + 32 * i;
            uint32_t off = (uint32_t)(r * 128 + ((ck8 ^ (r & 7)) << 4));
            cp_async16(sb + off, &Ag[(size_t)(m0 + r) * KD + k0 + 8 * ck8]);
            cp_async16(sb + 16384 + off, &Bg[(size_t)(n0 + r) * ldb + k0 + 8 * ck8]);
        }
        cp_commit();
    }

    int st = 0, stn = 2;
    for (int it = 0; it < NIT; it++) {
        if (it + 1 < NIT) cp_wait<1>(); else cp_wait<0>();
        __syncthreads();

        if (it + 2 < NIT) {
            const int k0 = (it + 2) << 6;
            const uint32_t sb = s0 + (uint32_t)(stn * 32768);
#pragma unroll
            for (int i = 0; i < 4; i++) {
                int r = cr + 32 * i;
                uint32_t off = (uint32_t)(r * 128 + ((ck8 ^ (r & 7)) << 4));
                cp_async16(sb + off, &Ag[(size_t)(m0 + r) * KD + k0 + 8 * ck8]);
                cp_async16(sb + 16384 + off, &Bg[(size_t)(n0 + r) * ldb + k0 + 8 * ck8]);
            }
            cp_commit();
        }

        const uint32_t bA = s0 + (uint32_t)(st * 32768);
        const uint32_t bB = bA + 16384;
#pragma unroll
        for (int ks = 0; ks < 4; ks++) {
            uint32_t af[4][4], bf[4][2];
#pragma unroll
            for (int ma = 0; ma < 4; ma++) {
                int rowm = mw + ma * 16 + a_row_in;
                int c8 = ks * 2 + a_k8off;
                ldmatrix_x4(af[ma], bA + (uint32_t)(rowm * 128 + ((c8 ^ (rowm & 7)) << 4)));
            }
#pragma unroll
            for (int na = 0; na < 4; na++) {
                int rown = nw + na * 8 + b_row_in;
                int c8 = ks * 2 + b_k8off;
                ldmatrix_x2(bf[na], bB + (uint32_t)(rown * 128 + ((c8 ^ (rown & 7)) << 4)));
            }
#pragma unroll
            for (int ma = 0; ma < 4; ma++)
#pragma unroll
                for (int na = 0; na < 4; na++)
                    mma_f16(acc[ma][na], af[ma], bf[na]);
        }

        st = (st == 2) ? 0 : st + 1;
        stn = (stn == 2) ? 0 : stn + 1;
    }

    // ---- epilogue (+ optional per-channel stats of fp32 outputs) ----
    const int rbase = m0 + mw + (lane >> 2);
    const int cbase = ncol + nw + (lane & 3) * 2;
    float s8[4][2], q8[4][2];
    if (STATS) {
#pragma unroll
        for (int na = 0; na < 4; na++)
#pragma unroll
            for (int j = 0; j < 2; j++) { s8[na][j] = 0.f; q8[na][j] = 0.f; }
    }
#pragma unroll
    for (int ma = 0; ma < 4; ma++)
#pragma unroll
        for (int na = 0; na < 4; na++) {
            float* d = acc[ma][na];
            float o[4];
#pragma unroll
            for (int e = 0; e < 4; e++) {
                float v = d[e] * scl;
                if (LEPI) v = LEAKY(v);
                o[e] = v;
                if (STATS) {
                    s8[na][e & 1] += v;
                    q8[na][e & 1] = fmaf(v, v, q8[na][e & 1]);
                }
            }
            size_t r0 = (size_t)(rbase + ma * 16) * ldc + cbase + na * 8;
            if (OUTH) {
                *(__half2*)&Ch[r0] = __floats2half2_rn(o[0], o[1]);
                *(__half2*)&Ch[r0 + (size_t)8 * ldc] = __floats2half2_rn(o[2], o[3]);
            } else {
                *(float2*)&Cf[r0]                   = make_float2(o[0], o[1]);
                *(float2*)&Cf[r0 + (size_t)8 * ldc] = make_float2(o[2], o[3]);
            }
        }

    if (STATS) {
        // reduce over the 8 lane-groups sharing the same columns (rows of warp)
#pragma unroll
        for (int m = 4; m <= 16; m <<= 1)
#pragma unroll
            for (int na = 0; na < 4; na++)
#pragma unroll
                for (int j = 0; j < 2; j++) {
                    s8[na][j] += __shfl_xor_sync(0xffffffffu, s8[na][j], m);
                    q8[na][j] += __shfl_xor_sync(0xffffffffu, q8[na][j], m);
                }
        __syncthreads();               // mainloop smem reads done; reuse dsm
        float* sb = (float*)dsm;       // [wid*4+l][na][j][2] = 512 floats
        if (lane < 4) {
#pragma unroll
            for (int na = 0; na < 4; na++)
#pragma unroll
                for (int j = 0; j < 2; j++) {
                    int idx = (((wid * 4 + lane) * 4 + na) * 2 + j) * 2;
                    sb[idx] = s8[na][j];
                    sb[idx + 1] = q8[na][j];
                }
        }
        __syncthreads();
        if (tid < 128) {
            int col = tid;
            int g = col >> 5;
            int na = (col & 31) >> 3;
            int l = (col & 7) >> 1;
            int e = col & 1;
            int i0 = (((2 * g) * 4 + l) * 4 + na) * 2 + e;
            int i1 = (((2 * g + 1) * 4 + l) * 4 + na) * 2 + e;
            float ssum = sb[i0 * 2] + sb[i1 * 2];
            float qsum = sb[i0 * 2 + 1] + sb[i1 * 2 + 1];
            int slot = blockIdx.x + gridDim.x * blockIdx.z;
            int statw = gridDim.y * 128;
            ps[slot * statw + n0 + col] = ssum;
            pq[slot * statw + n0 + col] = qsum;
        }
    }
}

// x -> fp16 (4 elems/thread)
__global__ void prep_x(const float* __restrict__ x)
{
    size_t i = (size_t)blockIdx.x * 256 + threadIdx.x;
    float4 v = ((const float4*)x)[i];
    __half2* dst = (__half2*)&g_Xh[i * 4];
    dst[0] = __floats2half2_rn(v.x, v.y);
    dst[1] = __floats2half2_rn(v.z, v.w);
}

// transpose + fp16-round weights: g_Wth[p][d][c] = W[c][d]
__global__ void prep_w(const float* __restrict__ Wq, const float* __restrict__ Wk,
                       const float* __restrict__ Wv)
{
    __shared__ float t[32][33];
    int p = blockIdx.z;
    const float* W = (p == 0) ? Wq : (p == 1) ? Wk : Wv;
    int c0 = blockIdx.x * 32, d0 = blockIdx.y * 32;
    int x = threadIdx.x, y = threadIdx.y;
#pragma unroll
    for (int r = 0; r < 4; r++)
        t[y + 8 * r][x] = W[(size_t)(c0 + y + 8 * r) * 256 + d0 + x];
    __syncthreads();
#pragma unroll
    for (int r = 0; r < 4; r++)
        g_Wth[(size_t)p * 65536 + (size_t)(d0 + y + 8 * r) * 256 + c0 + x] =
            __float2half_rn(t[x][y + 8 * r]);
}

// V half [b*4096+i][c] -> Vt half [b][c][i]
__global__ void transpose_v(const __half* __restrict__ V, __half* __restrict__ Vt)
{
    __shared__ __half t[32][40];
    int b = blockIdx.z;
    int i0 = blockIdx.x * 32;
    int c0 = blockIdx.y * 32;
    int x = threadIdx.x, y = threadIdx.y;
#pragma unroll
    for (int r = 0; r < 4; r++)
        t[y + 8 * r][x] = V[(size_t)(b * 4096 + i0 + y + 8 * r) * 256 + c0 + x];
    __syncthreads();
#pragma unroll
    for (int r = 0; r < 4; r++)
        Vt[(size_t)b * 1048576 + (size_t)(c0 + y + 8 * r) * 4096 + i0 + x] = t[x][y + 8 * r];
}

__global__ void finalize_qkv(const float* gq, const float* bq,
                             const float* gk, const float* bk,
                             const float* gv, const float* bv)
{
    int proj = blockIdx.x;
    int c = threadIdx.x;
    float s = 0.f, s2 = 0.f;
    for (int i = 0; i < 128; i++) {
        int o = i * 768 + proj * 256 + c;
        s += g_ps[o];
        s2 += g_pq[o];
    }
    float mu = s * (1.f / 16384.f);
    float var = s2 * (1.f / 16384.f) - mu * mu;
    float rs = rsqrtf(var + 1e-3f);
    const float* g = (proj == 0) ? gq : (proj == 1) ? gk : gv;
    const float* b = (proj == 0) ? bq : (proj == 1) ? bk : bv;
    float sc = g[c] * rs;
    g_scale[proj * 256 + c] = sc;
    g_shift[proj * 256 + c] = b[c] - mu * sc;
}

__global__ void finalize_soft(const float* __restrict__ g1)
{
    int c = threadIdx.x;
    float s = 0.f, s2 = 0.f;
    for (int i = 0; i < 128; i++) {
        int o = i * 256 + c;
        s += g_ps2[o];
        s2 += g_pq2[o];
    }
    float mu = s * (1.f / 16384.f);
    float var = s2 * (1.f / 16384.f) - mu * mu;
    g_sscale[c] = g1[c] * rsqrtf(var + 1e-3f);
}

// BN + LeakyReLU + fp16 round: g_Y (fp32) -> g_H (fp16)
__global__ void bnleaky_kern()
{
    size_t i4 = (size_t)blockIdx.x * 256 + threadIdx.x;
    int proj = (int)(i4 >> 20);
    int c4 = (int)(i4 & 63);
    float4 v = *(float4*)&g_Y[i4 * 4];
    int cb = proj * 256 + c4 * 4;
    float4 sc = *(float4*)&g_scale[cb];
    float4 sh = *(float4*)&g_shift[cb];
    v.x = fmaf(v.x, sc.x, sh.x); v.x = LEAKY(v.x);
    v.y = fmaf(v.y, sc.y, sh.y); v.y = LEAKY(v.y);
    v.z = fmaf(v.z, sc.z, sh.z); v.z = LEAKY(v.z);
    v.w = fmaf(v.w, sc.w, sh.w); v.w = LEAKY(v.w);
    __half2* dst = (__half2*)&g_H[i4 * 4];
    dst[0] = __floats2half2_rn(v.x, v.y);
    dst[1] = __floats2half2_rn(v.z, v.w);
}

// Spatial softmax of s_c * yout per (batch, channel): 2-pass (online max+sum).
__global__ void softmax_kern(const float* __restrict__ yout, float* __restrict__ out)
{
    int b = blockIdx.y;
    int c = blockIdx.x * 8 + (threadIdx.x & 7);
    int il = threadIdx.x >> 3;
    float s = g_sscale[c];
    const float* base = yout + (size_t)b * 1048576ull + c;
    float* obase = out + (size_t)b * 1048576ull + c;
    __shared__ float redm[256], reds[256];

    float m = -3.4e38f, sum = 0.f;
    for (int i = il; i < 4096; i += 32) {
        float v = s * base[(size_t)i * 256];
        if (v > m) {
            sum = sum * __expf(m - v) + 1.f;
            m = v;
        } else {
            sum += __expf(v - m);
        }
    }
    redm[threadIdx.x] = m;
    reds[threadIdx.x] = sum;
    __syncthreads();
    for (int st = 128; st >= 8; st >>= 1) {
        if (threadIdx.x < st) {
            float m1 = redm[threadIdx.x], s1 = reds[threadIdx.x];
            float m2 = redm[threadIdx.x + st], s2 = reds[threadIdx.x + st];
            float M = fmaxf(m1, m2);
            reds[threadIdx.x] = s1 * __expf(m1 - M) + s2 * __expf(m2 - M);
            redm[threadIdx.x] = M;
        }
        __syncthreads();
    }
    float M = redm[threadIdx.x & 7];
    float inv = 1.f / reds[threadIdx.x & 7];

    for (int i = il; i < 4096; i += 32)
        obase[(size_t)i * 256] = expf(s * base[(size_t)i * 256] - M) * inv;
}

// ---------------------------------------------------------------------------
extern "C" void kernel_launch(void* const* d_in, const int* in_sizes, int n_in,
                              void* d_out, int out_size)
{
    (void)in_sizes; (void)n_in; (void)out_size;
    const float* x  = (const float*)d_in[0];
    const float* Wq = (const float*)d_in[1];
    const float* gq = (const float*)d_in[2];
    const float* bq = (const float*)d_in[3];
    const float* Wk = (const float*)d_in[4];
    const float* gk = (const float*)d_in[5];
    const float* bk = (const float*)d_in[6];
    const float* Wv = (const float*)d_in[7];
    const float* gv = (const float*)d_in[8];
    const float* bv = (const float*)d_in[9];
    const float* g1 = (const float*)d_in[10];
    float* out = (float*)d_out;

    __half *pXh, *pWth, *pH, *pVth, *pPh;
    float *pY, *pyout, *pps, *ppq, *pps2, *ppq2;
    cudaGetSymbolAddress((void**)&pXh, g_Xh);
    cudaGetSymbolAddress((void**)&pWth, g_Wth);
    cudaGetSymbolAddress((void**)&pY, g_Y);
    cudaGetSymbolAddress((void**)&pH, g_H);
    cudaGetSymbolAddress((void**)&pVth, g_Vth);
    cudaGetSymbolAddress((void**)&pPh, g_Ph);
    cudaGetSymbolAddress((void**)&pyout, g_yout);
    cudaGetSymbolAddress((void**)&pps, g_ps);
    cudaGetSymbolAddress((void**)&ppq, g_pq);
    cudaGetSymbolAddress((void**)&pps2, g_ps2);
    cudaGetSymbolAddress((void**)&ppq2, g_pq2);

    const int GSMEM = 98304;   // 3-stage ring: 3 x (16KB A + 16KB B)
    cudaFuncSetAttribute(tc_gemm<false, true, false, true>,
                         cudaFuncAttributeMaxDynamicSharedMemorySize, GSMEM);
    cudaFuncSetAttribute(tc_gemm<true, false, true, false>,
                         cudaFuncAttributeMaxDynamicSharedMemorySize, GSMEM);
    cudaFuncSetAttribute(tc_gemm<false, false, false, true>,
                         cudaFuncAttributeMaxDynamicSharedMemorySize, GSMEM);

    // 0) condition operands to fp16
    prep_x<<<4096, 256>>>(x);
    prep_w<<<dim3(8, 8, 3), dim3(32, 8)>>>(Wq, Wk, Wv);

    // 1) QKV projections in ONE launch (fp16 in, fp32 out pre-BN) + BN stats
    tc_gemm<false, true, false, true><<<dim3(128, 6, 1), 256, GSMEM>>>(
        pXh, pWth, pY, 256, 256, 256, 0, 0, 0, 1.f, pps, ppq);

    // 2) finalize BN; apply BN+leaky -> fp16 Q,K,V
    finalize_qkv<<<3, 256>>>(gq, bq, gk, bk, gv, bv);
    bnleaky_kern<<<12288, 256>>>();

    // 3) V^T (fp16) for K-major B loads in GEMM2
    transpose_v<<<dim3(128, 8, 4), dim3(32, 8)>>>(pH + 2 * PROJ_ELEMS, pVth);

    // 4) P = leaky(Q K^T / 16)  -> fp16
    tc_gemm<true, false, true, false><<<dim3(32, 32, 4), 256, GSMEM>>>(
        pH, pH + PROJ_ELEMS, pPh,
        256, 256, 4096, QB_STRIDE, QB_STRIDE, PB_STRIDE, 0.0625f,
        nullptr, nullptr);

    // 5) yout = P @ V  (fp16 in, fp32 out) + softmax-variance stats
    tc_gemm<false, false, false, true><<<dim3(32, 2, 4), 256, GSMEM>>>(
        pPh, pVth, pyout,
        4096, 4096, 256, PB_STRIDE, QB_STRIDE, QB_STRIDE, 1.f, pps2, ppq2);

    // 6) softmax temperature; 2-pass spatial softmax
    finalize_soft<<<1, 256>>>(g1);
    softmax_kern<<<dim3(32, 4), 256>>>(pyout, out);
}